// round 5
// baseline (speedup 1.0000x reference)
#include <cuda_runtime.h>
#include <cstdint>

#define NUM_HEADS 8
#define IN_BITS   64
#define N_STATE   256
#define N_OUT     64
#define K_CONN    8
#define HASH      65536
#define BATCH     128
#define T_STEPS   128
#define TOTAL_IN  320   // IN_BITS + N_STATE

// Bit-packed threshold table: bit = (state_mem[n][a] >= 0.5). 2 MB, L2-resident.
__device__ uint32_t g_state_bits[N_STATE * (HASH / 32)];

#define PACK_LOHI(c, LO, HI)                                                    \
    LO = (uint32_t)((c).x & 255) | ((uint32_t)((c).y & 255) << 8)               \
       | ((uint32_t)((c).z & 255) << 16) | ((uint32_t)((c).w & 255) << 24);     \
    HI = (uint32_t)(((c).x >> 8) & 255) | ((uint32_t)(((c).y >> 8) & 255) << 8) \
       | ((uint32_t)(((c).z >> 8) & 255) << 16)                                 \
       | ((uint32_t)(((c).w >> 8) & 255) << 24);

// ---------------------------------------------------------------------------
// Prologue: pack state_mem (64 MB floats) into g_state_bits (2 MB). HBM-bound.
// ---------------------------------------------------------------------------
__global__ void pack_state_mem_kernel(const float* __restrict__ sm)
{
    const int tid  = blockIdx.x * blockDim.x + threadIdx.x;
    const int lane = threadIdx.x & 31;
    const int gw   = tid >> 5;
    const size_t base = (size_t)gw * 128;
    #pragma unroll
    for (int j = 0; j < 4; j++) {
        float v = sm[base + (size_t)j * 32 + lane];
        uint32_t b = __ballot_sync(0xFFFFFFFFu, v >= 0.5f);
        if (lane == 0) g_state_bits[gw * 4 + j] = b;
    }
}

__device__ __forceinline__ uint32_t smem_addr_u32(const void* p) {
    uint32_t a;
    asm("{ .reg .u64 t; cvta.to.shared.u64 t, %1; cvt.u32.u64 %0, t; }"
        : "=r"(a) : "l"(p));
    return a;
}

// ---------------------------------------------------------------------------
// Main scan: one 2-CTA cluster per batch. CTA rank r owns neurons
// [r*128, r*128+128); thread t = neuron r*128+t with its FULL 320-coeff row
// in registers. Per step: dot -> L2 gather -> shfl-pack 4 bits/word ->
// local + DSMEM store of next state -> mbarrier (128 local + 128 remote
// arrivals). Two CTAs (different batches) co-reside per SM -> each one's
// gather/exchange tail hides under the other's dp4a issue.
// ---------------------------------------------------------------------------
__global__ __launch_bounds__(128, 2) __cluster_dims__(2, 1, 1)
void ram_scan_kernel(const int*   __restrict__ bits,          // (B, T*64)
                     const int*   __restrict__ state_coeffs,  // (256, 320)
                     const int*   __restrict__ head_conn,     // (8, 64, 8)
                     const int*   __restrict__ head_coeffs,   // (8, 64, 8)
                     const float* __restrict__ head_mem,      // (8, 64, 65536)
                     float*       __restrict__ out)           // (B, 64)
{
    __shared__ uint32_t win_words[T_STEPS * 16];   // 8 KB window bytes
    __shared__ uint32_t stbuf[2][64];              // double-buffered 256-byte state
    __shared__ __align__(8) uint64_t mbar[1];

    const int      blk  = blockIdx.x;
    const int      b    = blk >> 1;                // batch = cluster id
    const uint32_t rank = (uint32_t)(blk & 1);     // cta rank in cluster
    const int      t    = threadIdx.x;
    const int      neuron = (int)(rank * 128u) + t;

    // ---- window bytes ----
    const int4* bits4 = reinterpret_cast<const int4*>(bits + (size_t)b * (T_STEPS * IN_BITS));
    for (int w = t; w < T_STEPS * 16; w += 128) {
        int4 v = bits4[w];
        win_words[w] = (uint32_t)(v.x & 1) | ((uint32_t)(v.y & 1) << 8)
                     | ((uint32_t)(v.z & 1) << 16) | ((uint32_t)(v.w & 1) << 24);
    }
    if (t < 64) stbuf[0][t] = 0u;

    const uint32_t mb = smem_addr_u32(mbar);
    if (t == 0)
        asm volatile("mbarrier.init.shared.b64 [%0], %1;" :: "r"(mb), "r"(256u) : "memory");

    // ---- full 320-coeff row into registers (lo/hi byte-packed) ----
    uint32_t wlo[16], whi[16], clo[64], chi[64];
    {
        const int4* crow = reinterpret_cast<const int4*>(state_coeffs + (size_t)neuron * TOTAL_IN);
        #pragma unroll
        for (int k = 0; k < 16; k++) { int4 c = crow[k];      PACK_LOHI(c, wlo[k], whi[k]); }
        #pragma unroll
        for (int k = 0; k < 64; k++) { int4 c = crow[16 + k]; PACK_LOHI(c, clo[k], chi[k]); }
    }

    __syncthreads();
    // cluster barrier: peer's mbarrier init + buffers visible before any remote op
    asm volatile("barrier.cluster.arrive.aligned;" ::: "memory");
    asm volatile("barrier.cluster.wait.aligned;"   ::: "memory");

    // ---- remote addresses (computed once) ----
    const uint32_t peer = rank ^ 1u;
    uint32_t mb_peer, rst0, rst1;
    asm("mapa.shared::cluster.u32 %0, %1, %2;" : "=r"(mb_peer) : "r"(mb), "r"(peer));
    {
        uint32_t l0 = smem_addr_u32(&stbuf[0][0]);
        uint32_t l1 = smem_addr_u32(&stbuf[1][0]);
        asm("mapa.shared::cluster.u32 %0, %1, %2;" : "=r"(rst0) : "r"(l0), "r"(peer));
        asm("mapa.shared::cluster.u32 %0, %1, %2;" : "=r"(rst1) : "r"(l1), "r"(peer));
    }

    const uint32_t* prow = g_state_bits + ((size_t)neuron << 11);   // 2048 words/row
    const uint4*    wv   = reinterpret_cast<const uint4*>(win_words);

    #pragma unroll 2
    for (int step = 0; step < T_STEPS; step++) {
        const int cur = step & 1, nxt = cur ^ 1;
        const uint4* st4 = reinterpret_cast<const uint4*>(stbuf[cur]);

        // 320-input dot: 160 dp4a in 8 chains
        uint32_t al[4] = {0u,0u,0u,0u}, ah[4] = {0u,0u,0u,0u};
        #pragma unroll
        for (int k = 0; k < 16; k++) {
            uint4 x = st4[k]; const int c = k & 3;
            al[c] = __dp4a(x.x, clo[k*4+0], al[c]); ah[c] = __dp4a(x.x, chi[k*4+0], ah[c]);
            al[c] = __dp4a(x.y, clo[k*4+1], al[c]); ah[c] = __dp4a(x.y, chi[k*4+1], ah[c]);
            al[c] = __dp4a(x.z, clo[k*4+2], al[c]); ah[c] = __dp4a(x.z, chi[k*4+2], ah[c]);
            al[c] = __dp4a(x.w, clo[k*4+3], al[c]); ah[c] = __dp4a(x.w, chi[k*4+3], ah[c]);
        }
        #pragma unroll
        for (int k = 0; k < 4; k++) {
            uint4 x = wv[step * 4 + k]; const int c = k & 3;
            al[c] = __dp4a(x.x, wlo[k*4+0], al[c]); ah[c] = __dp4a(x.x, whi[k*4+0], ah[c]);
            al[c] = __dp4a(x.y, wlo[k*4+1], al[c]); ah[c] = __dp4a(x.y, whi[k*4+1], ah[c]);
            al[c] = __dp4a(x.z, wlo[k*4+2], al[c]); ah[c] = __dp4a(x.z, whi[k*4+2], ah[c]);
            al[c] = __dp4a(x.w, wlo[k*4+3], al[c]); ah[c] = __dp4a(x.w, whi[k*4+3], ah[c]);
        }
        const uint32_t s    = ((al[0]+al[1]) + (al[2]+al[3]))
                            + ((((ah[0]+ah[1]) + (ah[2]+ah[3]))) << 8);
        const uint32_t addr = s & 0xFFFFu;

        // random gather (L2-resident 2 MB table)
        const uint32_t wword = __ldg(prow + (addr >> 5));
        const uint32_t bit   = (wword >> (addr & 31u)) & 1u;

        // pack 4 neighbor bits into one state word
        const uint32_t p1 = __shfl_down_sync(0xFFFFFFFFu, bit, 1);
        const uint32_t p2 = __shfl_down_sync(0xFFFFFFFFu, bit, 2);
        const uint32_t p3 = __shfl_down_sync(0xFFFFFFFFu, bit, 3);
        if ((t & 3) == 0) {
            const uint32_t word = bit | (p1 << 8) | (p2 << 16) | (p3 << 24);
            const int widx = neuron >> 2;
            stbuf[nxt][widx] = word;                              // local copy
            const uint32_t raddr = (nxt ? rst1 : rst0) + (uint32_t)(widx * 4);
            asm volatile("st.shared::cluster.u32 [%0], %1;"
                         :: "r"(raddr), "r"(word) : "memory");    // peer copy
        }
        // every thread arrives on BOTH barriers (after its reads + stores):
        asm volatile("mbarrier.arrive.release.cluster.shared::cluster.b64 _, [%0];"
                     :: "r"(mb_peer) : "memory");
        asm volatile("mbarrier.arrive.release.cluster.shared::cta.b64 _, [%0];"
                     :: "r"(mb) : "memory");
        // wait for 256 arrivals (phase parity = step & 1)
        {
            uint32_t done;
            asm volatile("{\n\t.reg .pred p;\n\t"
                "mbarrier.try_wait.parity.acquire.cluster.shared::cta.b64 p, [%1], %2;\n\t"
                "selp.b32 %0, 1, 0, p;\n\t}"
                : "=r"(done) : "r"(mb), "r"((uint32_t)cur) : "memory");
            while (!done) {
                asm volatile("{\n\t.reg .pred p;\n\t"
                    "mbarrier.try_wait.parity.acquire.cluster.shared::cta.b64 p, [%1], %2, 0x989680;\n\t"
                    "selp.b32 %0, 1, 0, p;\n\t}"
                    : "=r"(done) : "r"(mb), "r"((uint32_t)cur) : "memory");
            }
        }
    }

    // ---- Head readout: rank 0, threads 0..63 (full final state in stbuf[0]) ----
    if (rank == 0 && t < N_OUT) {
        const uint8_t* state_b = reinterpret_cast<const uint8_t*>(stbuf[0]);
        const int* lw = bits + (size_t)b * (T_STEPS * IN_BITS) + (T_STEPS * IN_BITS - 3);
        const int hidx = (lw[0] << 2) + (lw[1] << 1) + lw[2];     // 0..7
        const int o    = t;
        const int base = (hidx * N_OUT + o) * K_CONN;
        uint32_t addr = 0u;
        #pragma unroll
        for (int k = 0; k < K_CONN; k++) {
            int conn = __ldg(head_conn + base + k);
            uint32_t c = (uint32_t)__ldg(head_coeffs + base + k);
            addr += state_b[conn] ? c : 0u;
        }
        addr &= 0xFFFFu;
        out[(size_t)b * N_OUT + o] =
            __ldg(head_mem + (((size_t)(hidx * N_OUT + o)) << 16) + addr);
    }
}

extern "C" void kernel_launch(void* const* d_in, const int* in_sizes, int n_in,
                              void* d_out, int out_size)
{
    const int*   bits         = (const int*)  d_in[0];
    const int*   state_coeffs = (const int*)  d_in[1];
    const float* state_mem    = (const float*)d_in[2];
    const int*   head_conn    = (const int*)  d_in[3];
    const int*   head_coeffs  = (const int*)  d_in[4];
    const float* head_mem     = (const float*)d_in[5];
    float*       out          = (float*)      d_out;

    pack_state_mem_kernel<<<16384, 256>>>(state_mem);
    ram_scan_kernel<<<BATCH * 2, 128>>>(bits, state_coeffs,
                                        head_conn, head_coeffs, head_mem, out);
}